// round 12
// baseline (speedup 1.0000x reference)
#include <cuda_runtime.h>
#include <cuda.h>
#include <cuda_fp16.h>
#include <stdint.h>

// Problem sizes (fixed).
#define MM 8192
#define KK 4096
#define NN 4096

// GEMM tiling.
#define BM 256
#define BN 128
#define BKE 64                   // K elements (f16) per stage = 128 bytes
#define STAGES 4
#define KITERS (KK / BKE)        // 64
#define KCH 4                    // k16 chunks per stage

#define NTHREADS 512             // 16 warps: 8M x 2N, warp tile 32x64

// SMEM layout (dynamic):
//   [0..32)  full[4] mbarriers
//   [1024 + s*49152)          A stage tile: 256 rows x 128B (32KB, SW128)
//   [1024 + s*49152 + 32768)  B stage tile: 128 rows x 128B (16KB, SW128)
#define SMEM_FULL(s)  ((s) * 8)
#define SMEM_A_OFF(s) (1024 + (s) * 49152)
#define SMEM_B_OFF(s) (1024 + (s) * 49152 + 32768)
#define SMEM_TOTAL    (1024 + STAGES * 49152)

// Scratch (allocation-free: __device__ globals). fp16 operands.
__device__ __align__(1024) __half g_xh[(size_t)MM * KK];   // A f16 [M][K]
__device__ __align__(1024) __half g_wh[(size_t)NN * KK];   // B f16 [N][K] (k contiguous)

// ---------------------------------------------------------------------------
// PTX helpers (plain sm_103-safe)
// ---------------------------------------------------------------------------
__device__ __forceinline__ uint32_t smem_u32(const void* p) {
    uint32_t a;
    asm("{ .reg .u64 t; cvta.to.shared.u64 t, %1; cvt.u32.u64 %0, t; }" : "=r"(a) : "l"(p));
    return a;
}

#define MBAR_INIT(a, cnt) \
    asm volatile("mbarrier.init.shared.b64 [%0], %1;" :: "r"(a), "r"(cnt) : "memory")
#define MBAR_EXPECT_TX(a, bytes) \
    asm volatile("mbarrier.arrive.expect_tx.shared.b64 _, [%0], %1;" :: "r"(a), "r"(bytes) : "memory")

#define MBAR_WAIT(a, ph) do {                                                   \
    uint32_t _m = (a), _p = (ph), _d;                                           \
    asm volatile("{ .reg .pred p; mbarrier.try_wait.parity.acquire.cta.shared::cta.b64 p, [%1], %2; selp.b32 %0, 1, 0, p; }" \
        : "=r"(_d) : "r"(_m), "r"(_p) : "memory");                              \
    if (!_d) {                                                                  \
        asm volatile("{ .reg .pred P; L1_%=: mbarrier.try_wait.parity.acquire.cta.shared::cta.b64 P, [%0], %1, 0x989680; @P bra.uni L2_%=; bra.uni L1_%=; L2_%=: }" \
            :: "r"(_m), "r"(_p) : "memory");                                    \
    }                                                                           \
} while (0)

#define TMA_LOAD_2D(dst, map, cx, cy, bar) \
    asm volatile("cp.async.bulk.tensor.2d.shared::cta.global.tile.mbarrier::complete_tx::bytes [%0], [%1, {%2, %3}], [%4];" \
        :: "r"(dst), "l"(map), "r"(cx), "r"(cy), "r"(bar) : "memory")

#define LDSM_X4(r0, r1, r2, r3, addr) \
    asm volatile("ldmatrix.sync.aligned.m8n8.x4.shared.b16 {%0,%1,%2,%3}, [%4];" \
        : "=r"(r0), "=r"(r1), "=r"(r2), "=r"(r3) : "r"(addr))

// m16n8k16 f16 x f16 -> f32 accumulate.
#define MMA_F16(d, a, b) \
    asm volatile("mma.sync.aligned.m16n8k16.row.col.f32.f16.f16.f32 " \
        "{%0,%1,%2,%3}, {%4,%5,%6,%7}, {%8,%9}, {%0,%1,%2,%3};" \
        : "+f"((d)[0]), "+f"((d)[1]), "+f"((d)[2]), "+f"((d)[3]) \
        : "r"((a)[0]), "r"((a)[1]), "r"((a)[2]), "r"((a)[3]), "r"((b)[0]), "r"((b)[1]))

// ---------------------------------------------------------------------------
// Kernel 1: quantize x fp32 -> f16-of-int8 (round-half-even + clip), MLP=4.
// ---------------------------------------------------------------------------
__global__ void quantize_x_kernel(const float* __restrict__ x,
                                  const float* __restrict__ scale_ptr,
                                  __half* __restrict__ out) {
    int base = blockIdx.x * blockDim.x + threadIdx.x;
    int stride = gridDim.x * blockDim.x;
    float s = __ldg(scale_ptr);
    const float4* x4 = reinterpret_cast<const float4*>(x);
    uint2* o4 = reinterpret_cast<uint2*>(out);
    float4 v[4];
#pragma unroll
    for (int u = 0; u < 4; u++) v[u] = x4[base + u * stride];
#pragma unroll
    for (int u = 0; u < 4; u++) {
        int i = base + u * stride;
        int a = __float2int_rn(v[u].x / s);
        int b = __float2int_rn(v[u].y / s);
        int c = __float2int_rn(v[u].z / s);
        int d = __float2int_rn(v[u].w / s);
        a = min(127, max(-128, a)); b = min(127, max(-128, b));
        c = min(127, max(-128, c)); d = min(127, max(-128, d));
        uint32_t h0 = (uint32_t)__half_as_ushort(__int2half_rn(a))
                    | ((uint32_t)__half_as_ushort(__int2half_rn(b)) << 16);
        uint32_t h1 = (uint32_t)__half_as_ushort(__int2half_rn(c))
                    | ((uint32_t)__half_as_ushort(__int2half_rn(d)) << 16);
        uint2 q; q.x = h0; q.y = h1;
        o4[i] = q;
    }
}

// ---------------------------------------------------------------------------
// Kernel 2: repack weight int32 [K][N] -> f16 [N][K].
// ---------------------------------------------------------------------------
__global__ void repack_w_kernel(const int* __restrict__ w) {
    __shared__ __half s[32][128 + 4];
    int n0 = blockIdx.x * 32;
    int k0 = blockIdx.y * 128;
    int tid = threadIdx.x;
    int n = tid & 31, kb = tid >> 5;
#pragma unroll
    for (int i = 0; i < 16; i++) {
        int k = kb + i * 8;
        s[n][k] = __int2half_rn(w[(size_t)(k0 + k) * NN + (n0 + n)]);
    }
    __syncthreads();
    int kq = tid & 31, nn = tid >> 5;
#pragma unroll
    for (int i = 0; i < 4; i++) {
        int n2 = nn + i * 8;
        uint2 v = *reinterpret_cast<const uint2*>(&s[n2][kq * 4]);
        *reinterpret_cast<uint2*>(&g_wh[(size_t)(n0 + n2) * KK + k0 + kq * 4]) = v;
    }
}

// ---------------------------------------------------------------------------
// Kernel 3: f16 GEMM: TMA-fed 4-stage pipeline + ldmatrix + mma.sync.f16.
// CTA 256x128, 512 threads = 16 warps (8M x 2N), warp tile 32x64.
// 4 warps per SMSP for latency hiding.
// ---------------------------------------------------------------------------
__global__ void __launch_bounds__(NTHREADS, 1)
gemm_f16_mma_kernel(const __grid_constant__ CUtensorMap tma_a,
                    const __grid_constant__ CUtensorMap tma_b,
                    const float* __restrict__ bias,
                    const float* __restrict__ sa, const float* __restrict__ sbp,
                    float* __restrict__ C) {
    extern __shared__ char smem[];
    uint32_t sb = smem_u32(smem);
    int tid = threadIdx.x;
    int wid = tid >> 5;
    int lane = tid & 31;
    int wm = wid & 7;            // M offset wm*32
    int wn = wid >> 3;           // N offset wn*64
    int m_blk = blockIdx.y * BM;
    int n_blk = blockIdx.x * BN;

    if (tid == 0) {
#pragma unroll
        for (int s = 0; s < STAGES; s++) MBAR_INIT(sb + SMEM_FULL(s), 1);
    }
    __syncthreads();

    // Prologue: fill STAGES-1 stages.
    if (tid == 0) {
#pragma unroll
        for (int s = 0; s < STAGES - 1; s++) {
            MBAR_EXPECT_TX(sb + SMEM_FULL(s), 49152u);
            TMA_LOAD_2D(sb + SMEM_A_OFF(s), &tma_a, s * BKE, m_blk, sb + SMEM_FULL(s));
            TMA_LOAD_2D(sb + SMEM_B_OFF(s), &tma_b, s * BKE, n_blk, sb + SMEM_FULL(s));
        }
    }

    // Per-lane ldmatrix addressing (SW128: phys 16B-chunk = chunk ^ (row & 7)).
    int r7 = lane & 7;
    int a_row = wm * 32 + ((lane >> 3) & 1) * 8 + r7;   // + f*16
    int a_hi  = (lane >> 4) & 1;
    int b_row = wn * 64 + ((lane >> 4) & 1) * 8 + r7;   // + g*16
    int b_hi  = (lane >> 3) & 1;

    float acc[2][8][4];
#pragma unroll
    for (int f = 0; f < 2; f++)
#pragma unroll
        for (int j = 0; j < 8; j++)
#pragma unroll
            for (int e = 0; e < 4; e++) acc[f][j][e] = 0.0f;

    int s = 0, ph = 0;
    for (int it = 0; it < KITERS; it++) {
        MBAR_WAIT(sb + SMEM_FULL(s), (uint32_t)ph);

        uint32_t aBase = sb + SMEM_A_OFF(s) + (uint32_t)a_row * 128;
        uint32_t bBase = sb + SMEM_B_OFF(s) + (uint32_t)b_row * 128;

#pragma unroll
        for (int kc = 0; kc < KCH; kc++) {
            uint32_t aoff = (uint32_t)(((2 * kc + a_hi) ^ r7) << 4);
            uint32_t boff = (uint32_t)(((2 * kc + b_hi) ^ r7) << 4);

            uint32_t afr[2][4];
#pragma unroll
            for (int f = 0; f < 2; f++)
                LDSM_X4(afr[f][0], afr[f][1], afr[f][2], afr[f][3],
                        aBase + (uint32_t)(f * 16 * 128) + aoff);

            uint32_t bfr[8][2];
#pragma unroll
            for (int g = 0; g < 4; g++) {
                uint32_t t0, t1, t2, t3;
                LDSM_X4(t0, t1, t2, t3, bBase + (uint32_t)(g * 16 * 128) + boff);
                bfr[2 * g][0] = t0; bfr[2 * g][1] = t1;
                bfr[2 * g + 1][0] = t2; bfr[2 * g + 1][1] = t3;
            }

#pragma unroll
            for (int f = 0; f < 2; f++)
#pragma unroll
                for (int j = 0; j < 8; j++)
                    MMA_F16(acc[f][j], afr[f], bfr[j]);
        }

        __syncthreads();   // all warps done with stage s before refill

        if (tid == 0 && it + STAGES - 1 < KITERS) {
            int nk = it + STAGES - 1;
            int ns = nk % STAGES;
            MBAR_EXPECT_TX(sb + SMEM_FULL(ns), 49152u);
            TMA_LOAD_2D(sb + SMEM_A_OFF(ns), &tma_a, nk * BKE, m_blk, sb + SMEM_FULL(ns));
            TMA_LOAD_2D(sb + SMEM_B_OFF(ns), &tma_b, nk * BKE, n_blk, sb + SMEM_FULL(ns));
        }

        if (++s == STAGES) { s = 0; ph ^= 1; }
    }

    // Epilogue: dequant + bias, float2 stores.
    float scale = __ldg(sa) * __ldg(sbp);
    int r = lane >> 2;
    int c2 = (lane & 3) * 2;
#pragma unroll
    for (int f = 0; f < 2; f++) {
        int row0 = m_blk + wm * 32 + f * 16 + r;
#pragma unroll
        for (int j = 0; j < 8; j++) {
            int col = n_blk + wn * 64 + j * 8 + c2;
            float2 bv = *reinterpret_cast<const float2*>(bias + col);
            float2 o0, o1;
            o0.x = acc[f][j][0] * scale + bv.x;
            o0.y = acc[f][j][1] * scale + bv.y;
            o1.x = acc[f][j][2] * scale + bv.x;
            o1.y = acc[f][j][3] * scale + bv.y;
            *reinterpret_cast<float2*>(C + (size_t)row0 * NN + col) = o0;
            *reinterpret_cast<float2*>(C + (size_t)(row0 + 8) * NN + col) = o1;
        }
    }
}

// ---------------------------------------------------------------------------
// Host launch
// ---------------------------------------------------------------------------
typedef CUresult (*EncodeTiledFn)(
    CUtensorMap*, CUtensorMapDataType, cuuint32_t, void*,
    const cuuint64_t*, const cuuint64_t*, const cuuint32_t*, const cuuint32_t*,
    CUtensorMapInterleave, CUtensorMapSwizzle, CUtensorMapL2promotion,
    CUtensorMapFloatOOBfill);

static void build_tmap_f16(EncodeTiledFn enc, CUtensorMap* out, void* ptr,
                           uint64_t dim0_elems, uint64_t dim1, uint32_t box_rows) {
    cuuint64_t dims[2] = {dim0_elems, dim1};
    cuuint64_t strides[1] = {dim0_elems * 2};   // bytes
    cuuint32_t box[2] = {BKE, box_rows};        // 64 f16 = 128B row
    cuuint32_t estr[2] = {1, 1};
    enc(out, CU_TENSOR_MAP_DATA_TYPE_FLOAT16, 2, ptr, dims, strides, box, estr,
        CU_TENSOR_MAP_INTERLEAVE_NONE, CU_TENSOR_MAP_SWIZZLE_128B,
        CU_TENSOR_MAP_L2_PROMOTION_L2_128B, CU_TENSOR_MAP_FLOAT_OOB_FILL_NONE);
}

extern "C" void kernel_launch(void* const* d_in, const int* in_sizes, int n_in,
                              void* d_out, int out_size) {
    const float* x      = (const float*)d_in[0];
    const int*   weight = (const int*)  d_in[1];
    const float* bias   = (const float*)d_in[2];
    const float* in_sc  = (const float*)d_in[3];
    const float* w_sc   = (const float*)d_in[4];
    float*       out    = (float*)d_out;

    __half* xh; cudaGetSymbolAddress((void**)&xh, g_xh);
    __half* wh; cudaGetSymbolAddress((void**)&wh, g_wh);

    // 1) quantize activations -> f16
    {
        int n4 = (MM * KK) / 4;
        int threads = 256;
        int blocks = n4 / (threads * 4);
        quantize_x_kernel<<<blocks, threads>>>(x, in_sc, xh);
    }
    // 2) repack + transpose weight -> f16
    {
        dim3 grid(NN / 32, KK / 128);
        repack_w_kernel<<<grid, 256>>>(weight);
    }
    // 3) tensor-core GEMM (f16 HMMA, 256x128 CTA, 16 warps / 4 per SMSP)
    {
        EncodeTiledFn enc = nullptr;
        cudaDriverEntryPointQueryResult qr;
        cudaGetDriverEntryPointByVersion("cuTensorMapEncodeTiled", (void**)&enc,
                                         12030, cudaEnableDefault, &qr);
        CUtensorMap tma_a, tma_b;
        build_tmap_f16(enc, &tma_a, xh, KK, MM, 256);
        build_tmap_f16(enc, &tma_b, wh, KK, NN, 128);

        cudaFuncSetAttribute(gemm_f16_mma_kernel,
                             cudaFuncAttributeMaxDynamicSharedMemorySize, SMEM_TOTAL);
        dim3 grid(NN / BN, MM / BM);
        gemm_f16_mma_kernel<<<grid, NTHREADS, SMEM_TOTAL>>>(tma_a, tma_b, bias,
                                                            in_sc, w_sc, out);
    }
}

// round 14
// speedup vs baseline: 1.1761x; 1.1761x over previous
#include <cuda_runtime.h>
#include <cuda.h>
#include <cuda_fp16.h>
#include <stdint.h>

// Problem sizes (fixed).
#define MM 8192
#define KK 4096
#define NN 4096

// GEMM tiling.
#define BM 256
#define BN 128
#define BKE 64                   // K elements (f16) per stage = 128 bytes
#define STAGES 4
#define KITERS (KK / BKE)        // 64
#define KCH 4                    // k16 chunks per stage

// SMEM layout (dynamic):
//   [0..32)   full[4] mbarriers (tx, producer->consumers)
//   [64..96)  empty[4] mbarriers (count 8, consumers->producer)
//   [1024 + s*49152)          A stage tile: 256 rows x 128B (32KB, SW128)
//   [1024 + s*49152 + 32768)  B stage tile: 128 rows x 128B (16KB, SW128)
#define SMEM_FULL(s)  ((s) * 8)
#define SMEM_EMPTY(s) (64 + (s) * 8)
#define SMEM_A_OFF(s) (1024 + (s) * 49152)
#define SMEM_B_OFF(s) (1024 + (s) * 49152 + 32768)
#define SMEM_TOTAL    (1024 + STAGES * 49152)

// Scratch (allocation-free: __device__ globals). fp16 operands.
__device__ __align__(1024) __half g_xh[(size_t)MM * KK];   // A f16 [M][K]
__device__ __align__(1024) __half g_wh[(size_t)NN * KK];   // B f16 [N][K] (k contiguous)

// ---------------------------------------------------------------------------
// PTX helpers (plain sm_103-safe)
// ---------------------------------------------------------------------------
__device__ __forceinline__ uint32_t smem_u32(const void* p) {
    uint32_t a;
    asm("{ .reg .u64 t; cvta.to.shared.u64 t, %1; cvt.u32.u64 %0, t; }" : "=r"(a) : "l"(p));
    return a;
}
__device__ __forceinline__ uint32_t elect_one() {
    uint32_t p;
    asm volatile("{ .reg .pred q; elect.sync _|q, 0xFFFFFFFF; selp.b32 %0, 1, 0, q; }" : "=r"(p));
    return p;
}

#define MBAR_INIT(a, cnt) \
    asm volatile("mbarrier.init.shared.b64 [%0], %1;" :: "r"(a), "r"(cnt) : "memory")
#define MBAR_EXPECT_TX(a, bytes) \
    asm volatile("mbarrier.arrive.expect_tx.shared.b64 _, [%0], %1;" :: "r"(a), "r"(bytes) : "memory")
#define MBAR_ARRIVE(a) \
    asm volatile("mbarrier.arrive.release.cta.shared.b64 _, [%0];" :: "r"(a) : "memory")

#define MBAR_WAIT(a, ph) do {                                                   \
    uint32_t _m = (a), _p = (ph), _d;                                           \
    asm volatile("{ .reg .pred p; mbarrier.try_wait.parity.acquire.cta.shared::cta.b64 p, [%1], %2; selp.b32 %0, 1, 0, p; }" \
        : "=r"(_d) : "r"(_m), "r"(_p) : "memory");                              \
    if (!_d) {                                                                  \
        asm volatile("{ .reg .pred P; L1_%=: mbarrier.try_wait.parity.acquire.cta.shared::cta.b64 P, [%0], %1, 0x989680; @P bra.uni L2_%=; bra.uni L1_%=; L2_%=: }" \
            :: "r"(_m), "r"(_p) : "memory");                                    \
    }                                                                           \
} while (0)

#define TMA_LOAD_2D(dst, map, cx, cy, bar) \
    asm volatile("cp.async.bulk.tensor.2d.shared::cta.global.tile.mbarrier::complete_tx::bytes [%0], [%1, {%2, %3}], [%4];" \
        :: "r"(dst), "l"(map), "r"(cx), "r"(cy), "r"(bar) : "memory")

#define LDSM_X4(r0, r1, r2, r3, addr) \
    asm volatile("ldmatrix.sync.aligned.m8n8.x4.shared.b16 {%0,%1,%2,%3}, [%4];" \
        : "=r"(r0), "=r"(r1), "=r"(r2), "=r"(r3) : "r"(addr))

// m16n8k16 f16 x f16 -> f32 accumulate.
#define MMA_F16(d, a, b) \
    asm volatile("mma.sync.aligned.m16n8k16.row.col.f32.f16.f16.f32 " \
        "{%0,%1,%2,%3}, {%4,%5,%6,%7}, {%8,%9}, {%0,%1,%2,%3};" \
        : "+f"((d)[0]), "+f"((d)[1]), "+f"((d)[2]), "+f"((d)[3]) \
        : "r"((a)[0]), "r"((a)[1]), "r"((a)[2]), "r"((a)[3]), "r"((b)[0]), "r"((b)[1]))

// ---------------------------------------------------------------------------
// Kernel 1: quantize x fp32 -> f16-of-int8 (round-half-even + clip), MLP=4.
// ---------------------------------------------------------------------------
__global__ void quantize_x_kernel(const float* __restrict__ x,
                                  const float* __restrict__ scale_ptr,
                                  __half* __restrict__ out) {
    int base = blockIdx.x * blockDim.x + threadIdx.x;
    int stride = gridDim.x * blockDim.x;
    float s = __ldg(scale_ptr);
    const float4* x4 = reinterpret_cast<const float4*>(x);
    uint2* o4 = reinterpret_cast<uint2*>(out);
    float4 v[4];
#pragma unroll
    for (int u = 0; u < 4; u++) v[u] = x4[base + u * stride];
#pragma unroll
    for (int u = 0; u < 4; u++) {
        int i = base + u * stride;
        int a = __float2int_rn(v[u].x / s);
        int b = __float2int_rn(v[u].y / s);
        int c = __float2int_rn(v[u].z / s);
        int d = __float2int_rn(v[u].w / s);
        a = min(127, max(-128, a)); b = min(127, max(-128, b));
        c = min(127, max(-128, c)); d = min(127, max(-128, d));
        uint32_t h0 = (uint32_t)__half_as_ushort(__int2half_rn(a))
                    | ((uint32_t)__half_as_ushort(__int2half_rn(b)) << 16);
        uint32_t h1 = (uint32_t)__half_as_ushort(__int2half_rn(c))
                    | ((uint32_t)__half_as_ushort(__int2half_rn(d)) << 16);
        uint2 q; q.x = h0; q.y = h1;
        o4[i] = q;
    }
}

// ---------------------------------------------------------------------------
// Kernel 2: repack weight int32 [K][N] -> f16 [N][K].
// ---------------------------------------------------------------------------
__global__ void repack_w_kernel(const int* __restrict__ w) {
    __shared__ __half s[32][128 + 4];
    int n0 = blockIdx.x * 32;
    int k0 = blockIdx.y * 128;
    int tid = threadIdx.x;
    int n = tid & 31, kb = tid >> 5;
#pragma unroll
    for (int i = 0; i < 16; i++) {
        int k = kb + i * 8;
        s[n][k] = __int2half_rn(w[(size_t)(k0 + k) * NN + (n0 + n)]);
    }
    __syncthreads();
    int kq = tid & 31, nn = tid >> 5;
#pragma unroll
    for (int i = 0; i < 4; i++) {
        int n2 = nn + i * 8;
        uint2 v = *reinterpret_cast<const uint2*>(&s[n2][kq * 4]);
        *reinterpret_cast<uint2*>(&g_wh[(size_t)(n0 + n2) * KK + k0 + kq * 4]) = v;
    }
}

// ---------------------------------------------------------------------------
// Kernel 3: f16 GEMM. CTA 256x128, 256 threads = 8 warps (4M x 2N),
// warp tile 64x64. 4-stage TMA pipeline with EMBEDDED producer:
// no per-iteration __syncthreads — consumers free-run, each warp
// release-arrives empty(s); warp 0's elected lane waits empty and refills.
// Prologue fills ALL 4 stages (slices 0..3); refill provides slices 4..63.
// ---------------------------------------------------------------------------
__global__ void __launch_bounds__(256, 1)
gemm_f16_mma_kernel(const __grid_constant__ CUtensorMap tma_a,
                    const __grid_constant__ CUtensorMap tma_b,
                    const float* __restrict__ bias,
                    const float* __restrict__ sa, const float* __restrict__ sbp,
                    float* __restrict__ C) {
    extern __shared__ char smem[];
    uint32_t sb = smem_u32(smem);
    int tid = threadIdx.x;
    int wid = tid >> 5;
    int lane = tid & 31;
    int wm = wid & 3;            // M offset wm*64
    int wn = wid >> 2;           // N offset wn*64
    int m_blk = blockIdx.y * BM;
    int n_blk = blockIdx.x * BN;

    if (tid == 0) {
#pragma unroll
        for (int s = 0; s < STAGES; s++) {
            MBAR_INIT(sb + SMEM_FULL(s), 1);
            MBAR_INIT(sb + SMEM_EMPTY(s), 8);
        }
    }
    __syncthreads();

    // Prologue: fill ALL STAGES stages (slices 0..STAGES-1).
    if (tid == 0) {
#pragma unroll
        for (int s = 0; s < STAGES; s++) {
            MBAR_EXPECT_TX(sb + SMEM_FULL(s), 49152u);
            TMA_LOAD_2D(sb + SMEM_A_OFF(s), &tma_a, s * BKE, m_blk, sb + SMEM_FULL(s));
            TMA_LOAD_2D(sb + SMEM_B_OFF(s), &tma_b, s * BKE, n_blk, sb + SMEM_FULL(s));
        }
    }

    // Per-lane ldmatrix addressing (SW128: phys 16B-chunk = chunk ^ (row & 7)).
    int r7 = lane & 7;
    int a_row = wm * 64 + ((lane >> 3) & 1) * 8 + r7;   // + f*16
    int a_hi  = (lane >> 4) & 1;
    int b_row = wn * 64 + ((lane >> 4) & 1) * 8 + r7;   // + g*16
    int b_hi  = (lane >> 3) & 1;

    float acc[4][8][4];
#pragma unroll
    for (int f = 0; f < 4; f++)
#pragma unroll
        for (int j = 0; j < 8; j++)
#pragma unroll
            for (int e = 0; e < 4; e++) acc[f][j][e] = 0.0f;

    int is_refiller = (wid == 0) ? (int)elect_one() : 0;

    int s = 0, ph = 0;
    int eph = 0;                 // producer parity for empty barriers
    for (int it = 0; it < KITERS; it++) {
        // Refill the stage consumed at iteration it-1 with k-slice it+STAGES-1.
        // Slice nk lands in slot nk % STAGES == (it-1) % STAGES.
        if (is_refiller && it > 0 && it + STAGES - 1 < KITERS) {
            int ns = (it - 1) % STAGES;
            MBAR_WAIT(sb + SMEM_EMPTY(ns), (uint32_t)eph);
            MBAR_EXPECT_TX(sb + SMEM_FULL(ns), 49152u);
            int nk = it + STAGES - 1;
            TMA_LOAD_2D(sb + SMEM_A_OFF(ns), &tma_a, nk * BKE, m_blk, sb + SMEM_FULL(ns));
            TMA_LOAD_2D(sb + SMEM_B_OFF(ns), &tma_b, nk * BKE, n_blk, sb + SMEM_FULL(ns));
            if (ns == STAGES - 1) eph ^= 1;
        }

        MBAR_WAIT(sb + SMEM_FULL(s), (uint32_t)ph);

        uint32_t aBase = sb + SMEM_A_OFF(s) + (uint32_t)a_row * 128;
        uint32_t bBase = sb + SMEM_B_OFF(s) + (uint32_t)b_row * 128;

#pragma unroll
        for (int kc = 0; kc < KCH; kc++) {
            uint32_t aoff = (uint32_t)(((2 * kc + a_hi) ^ r7) << 4);
            uint32_t boff = (uint32_t)(((2 * kc + b_hi) ^ r7) << 4);

            uint32_t afr[4][4];
#pragma unroll
            for (int f = 0; f < 4; f++)
                LDSM_X4(afr[f][0], afr[f][1], afr[f][2], afr[f][3],
                        aBase + (uint32_t)(f * 16 * 128) + aoff);

            uint32_t bfr[8][2];
#pragma unroll
            for (int g = 0; g < 4; g++) {
                uint32_t t0, t1, t2, t3;
                LDSM_X4(t0, t1, t2, t3, bBase + (uint32_t)(g * 16 * 128) + boff);
                bfr[2 * g][0] = t0; bfr[2 * g][1] = t1;
                bfr[2 * g + 1][0] = t2; bfr[2 * g + 1][1] = t3;
            }

#pragma unroll
            for (int f = 0; f < 4; f++)
#pragma unroll
                for (int j = 0; j < 8; j++)
                    MMA_F16(acc[f][j], afr[f], bfr[j]);
        }

        // Release this stage (one arrive per warp; no CTA barrier).
        if (elect_one()) MBAR_ARRIVE(sb + SMEM_EMPTY(s));

        if (++s == STAGES) { s = 0; ph ^= 1; }
    }

    // Epilogue: dequant + bias, float2 stores.
    float scale = __ldg(sa) * __ldg(sbp);
    int r = lane >> 2;
    int c2 = (lane & 3) * 2;
#pragma unroll
    for (int f = 0; f < 4; f++) {
        int row0 = m_blk + wm * 64 + f * 16 + r;
#pragma unroll
        for (int j = 0; j < 8; j++) {
            int col = n_blk + wn * 64 + j * 8 + c2;
            float2 bv = *reinterpret_cast<const float2*>(bias + col);
            float2 o0, o1;
            o0.x = acc[f][j][0] * scale + bv.x;
            o0.y = acc[f][j][1] * scale + bv.y;
            o1.x = acc[f][j][2] * scale + bv.x;
            o1.y = acc[f][j][3] * scale + bv.y;
            *reinterpret_cast<float2*>(C + (size_t)row0 * NN + col) = o0;
            *reinterpret_cast<float2*>(C + (size_t)(row0 + 8) * NN + col) = o1;
        }
    }
}

// ---------------------------------------------------------------------------
// Host launch
// ---------------------------------------------------------------------------
typedef CUresult (*EncodeTiledFn)(
    CUtensorMap*, CUtensorMapDataType, cuuint32_t, void*,
    const cuuint64_t*, const cuuint64_t*, const cuuint32_t*, const cuuint32_t*,
    CUtensorMapInterleave, CUtensorMapSwizzle, CUtensorMapL2promotion,
    CUtensorMapFloatOOBfill);

static void build_tmap_f16(EncodeTiledFn enc, CUtensorMap* out, void* ptr,
                           uint64_t dim0_elems, uint64_t dim1, uint32_t box_rows) {
    cuuint64_t dims[2] = {dim0_elems, dim1};
    cuuint64_t strides[1] = {dim0_elems * 2};   // bytes
    cuuint32_t box[2] = {BKE, box_rows};        // 64 f16 = 128B row
    cuuint32_t estr[2] = {1, 1};
    enc(out, CU_TENSOR_MAP_DATA_TYPE_FLOAT16, 2, ptr, dims, strides, box, estr,
        CU_TENSOR_MAP_INTERLEAVE_NONE, CU_TENSOR_MAP_SWIZZLE_128B,
        CU_TENSOR_MAP_L2_PROMOTION_L2_128B, CU_TENSOR_MAP_FLOAT_OOB_FILL_NONE);
}

extern "C" void kernel_launch(void* const* d_in, const int* in_sizes, int n_in,
                              void* d_out, int out_size) {
    const float* x      = (const float*)d_in[0];
    const int*   weight = (const int*)  d_in[1];
    const float* bias   = (const float*)d_in[2];
    const float* in_sc  = (const float*)d_in[3];
    const float* w_sc   = (const float*)d_in[4];
    float*       out    = (float*)d_out;

    __half* xh; cudaGetSymbolAddress((void**)&xh, g_xh);
    __half* wh; cudaGetSymbolAddress((void**)&wh, g_wh);

    // 1) quantize activations -> f16
    {
        int n4 = (MM * KK) / 4;
        int threads = 256;
        int blocks = n4 / (threads * 4);
        quantize_x_kernel<<<blocks, threads>>>(x, in_sc, xh);
    }
    // 2) repack + transpose weight -> f16
    {
        dim3 grid(NN / 32, KK / 128);
        repack_w_kernel<<<grid, 256>>>(weight);
    }
    // 3) tensor-core GEMM (f16 HMMA, 256x128 CTA, embedded-producer pipeline)
    {
        EncodeTiledFn enc = nullptr;
        cudaDriverEntryPointQueryResult qr;
        cudaGetDriverEntryPointByVersion("cuTensorMapEncodeTiled", (void**)&enc,
                                         12030, cudaEnableDefault, &qr);
        CUtensorMap tma_a, tma_b;
        build_tmap_f16(enc, &tma_a, xh, KK, MM, 256);
        build_tmap_f16(enc, &tma_b, wh, KK, NN, 128);

        cudaFuncSetAttribute(gemm_f16_mma_kernel,
                             cudaFuncAttributeMaxDynamicSharedMemorySize, SMEM_TOTAL);
        dim3 grid(NN / BN, MM / BM);
        gemm_f16_mma_kernel<<<grid, 256, SMEM_TOTAL>>>(tma_a, tma_b, bias,
                                                       in_sc, w_sc, out);
    }
}

// round 15
// speedup vs baseline: 1.1838x; 1.0065x over previous
#include <cuda_runtime.h>
#include <cuda.h>
#include <cuda_fp16.h>
#include <stdint.h>

// Problem sizes (fixed).
#define MM 8192
#define KK 4096
#define NN 4096

// GEMM tiling.
#define BM 256
#define BN 128
#define BKE 64                   // K elements (f16) per slice = 128 bytes
#define NSLOTS 4                 // slice buffers
#define GROUPS 2                 // barrier groups (2 slices each)
#define KITERS (KK / BKE)        // 64 slices
#define KPAIRS (KITERS / 2)      // 32 pairs
#define KCH 4                    // k16 chunks per slice

// SMEM layout (dynamic):
//   [0..16)   full[2] mbarriers (tx, one per group)
//   [64..80)  empty[2] mbarriers (count 8)
//   [1024 + s*49152)          A slice buf: 256 rows x 128B (32KB, SW128)
//   [1024 + s*49152 + 32768)  B slice buf: 128 rows x 128B (16KB, SW128)
#define SMEM_FULL(g)  ((g) * 8)
#define SMEM_EMPTY(g) (64 + (g) * 8)
#define SMEM_A_OFF(s) (1024 + (s) * 49152)
#define SMEM_B_OFF(s) (1024 + (s) * 49152 + 32768)
#define SMEM_TOTAL    (1024 + NSLOTS * 49152)

#define PAIR_BYTES 98304u        // 2 slices x (32KB A + 16KB B)

// Scratch (allocation-free: __device__ globals). fp16 operands.
__device__ __align__(1024) __half g_xh[(size_t)MM * KK];   // A f16 [M][K]
__device__ __align__(1024) __half g_wh[(size_t)NN * KK];   // B f16 [N][K] (k contiguous)

// ---------------------------------------------------------------------------
// PTX helpers (plain sm_103-safe)
// ---------------------------------------------------------------------------
__device__ __forceinline__ uint32_t smem_u32(const void* p) {
    uint32_t a;
    asm("{ .reg .u64 t; cvta.to.shared.u64 t, %1; cvt.u32.u64 %0, t; }" : "=r"(a) : "l"(p));
    return a;
}
__device__ __forceinline__ uint32_t elect_one() {
    uint32_t p;
    asm volatile("{ .reg .pred q; elect.sync _|q, 0xFFFFFFFF; selp.b32 %0, 1, 0, q; }" : "=r"(p));
    return p;
}

#define MBAR_INIT(a, cnt) \
    asm volatile("mbarrier.init.shared.b64 [%0], %1;" :: "r"(a), "r"(cnt) : "memory")
#define MBAR_EXPECT_TX(a, bytes) \
    asm volatile("mbarrier.arrive.expect_tx.shared.b64 _, [%0], %1;" :: "r"(a), "r"(bytes) : "memory")
#define MBAR_ARRIVE(a) \
    asm volatile("mbarrier.arrive.release.cta.shared.b64 _, [%0];" :: "r"(a) : "memory")

#define MBAR_WAIT(a, ph) do {                                                   \
    uint32_t _m = (a), _p = (ph), _d;                                           \
    asm volatile("{ .reg .pred p; mbarrier.try_wait.parity.acquire.cta.shared::cta.b64 p, [%1], %2; selp.b32 %0, 1, 0, p; }" \
        : "=r"(_d) : "r"(_m), "r"(_p) : "memory");                              \
    if (!_d) {                                                                  \
        asm volatile("{ .reg .pred P; L1_%=: mbarrier.try_wait.parity.acquire.cta.shared::cta.b64 P, [%0], %1, 0x989680; @P bra.uni L2_%=; bra.uni L1_%=; L2_%=: }" \
            :: "r"(_m), "r"(_p) : "memory");                                    \
    }                                                                           \
} while (0)

#define TMA_LOAD_2D(dst, map, cx, cy, bar) \
    asm volatile("cp.async.bulk.tensor.2d.shared::cta.global.tile.mbarrier::complete_tx::bytes [%0], [%1, {%2, %3}], [%4];" \
        :: "r"(dst), "l"(map), "r"(cx), "r"(cy), "r"(bar) : "memory")

#define LDSM_X4(r0, r1, r2, r3, addr) \
    asm volatile("ldmatrix.sync.aligned.m8n8.x4.shared.b16 {%0,%1,%2,%3}, [%4];" \
        : "=r"(r0), "=r"(r1), "=r"(r2), "=r"(r3) : "r"(addr))

// m16n8k16 f16 x f16 -> f32 accumulate.
#define MMA_F16(d, a, b) \
    asm volatile("mma.sync.aligned.m16n8k16.row.col.f32.f16.f16.f32 " \
        "{%0,%1,%2,%3}, {%4,%5,%6,%7}, {%8,%9}, {%0,%1,%2,%3};" \
        : "+f"((d)[0]), "+f"((d)[1]), "+f"((d)[2]), "+f"((d)[3]) \
        : "r"((a)[0]), "r"((a)[1]), "r"((a)[2]), "r"((a)[3]), "r"((b)[0]), "r"((b)[1]))

// ---------------------------------------------------------------------------
// Kernel 1 (merged prep): blocks [0, 8192) quantize x; blocks [8192, 12288)
// repack the weight. Concurrent execution fills HBM bandwidth gaps.
// ---------------------------------------------------------------------------
#define QBLOCKS 8192
#define QSTRIDE (QBLOCKS * 256)

__global__ void __launch_bounds__(256)
prep_kernel(const float* __restrict__ x,
            const float* __restrict__ scale_ptr,
            const int* __restrict__ w) {
    __shared__ __half sh[32][128 + 4];
    int bx = blockIdx.x;
    int tid = threadIdx.x;

    if (bx < QBLOCKS) {
        // ---- quantize x fp32 -> f16-of-int8 (round-half-even + clip) ----
        int base = bx * 256 + tid;
        float s = __ldg(scale_ptr);
        const float4* x4 = reinterpret_cast<const float4*>(x);
        uint2* o4 = reinterpret_cast<uint2*>(g_xh);
        float4 v[4];
#pragma unroll
        for (int u = 0; u < 4; u++) v[u] = x4[base + u * QSTRIDE];
#pragma unroll
        for (int u = 0; u < 4; u++) {
            int i = base + u * QSTRIDE;
            int a = __float2int_rn(v[u].x / s);
            int b = __float2int_rn(v[u].y / s);
            int c = __float2int_rn(v[u].z / s);
            int d = __float2int_rn(v[u].w / s);
            a = min(127, max(-128, a)); b = min(127, max(-128, b));
            c = min(127, max(-128, c)); d = min(127, max(-128, d));
            uint32_t h0 = (uint32_t)__half_as_ushort(__int2half_rn(a))
                        | ((uint32_t)__half_as_ushort(__int2half_rn(b)) << 16);
            uint32_t h1 = (uint32_t)__half_as_ushort(__int2half_rn(c))
                        | ((uint32_t)__half_as_ushort(__int2half_rn(d)) << 16);
            uint2 q; q.x = h0; q.y = h1;
            o4[i] = q;
        }
    } else {
        // ---- repack weight int32 [K][N] -> f16 [N][K] ----
        int rb = bx - QBLOCKS;                // 0..4095
        int n0 = (rb & 127) * 32;             // 128 n-blocks
        int k0 = (rb >> 7) * 128;             // 32 k-blocks
        int n = tid & 31, kb = tid >> 5;
#pragma unroll
        for (int i = 0; i < 16; i++) {
            int k = kb + i * 8;
            sh[n][k] = __int2half_rn(w[(size_t)(k0 + k) * NN + (n0 + n)]);
        }
        __syncthreads();
        int kq = tid & 31, nn = tid >> 5;
#pragma unroll
        for (int i = 0; i < 4; i++) {
            int n2 = nn + i * 8;
            uint2 v = *reinterpret_cast<const uint2*>(&sh[n2][kq * 4]);
            *reinterpret_cast<uint2*>(&g_wh[(size_t)(n0 + n2) * KK + k0 + kq * 4]) = v;
        }
    }
}

// ---------------------------------------------------------------------------
// Kernel 2: f16 GEMM. CTA 256x128, 256 threads = 8 warps (4M x 2N),
// warp tile 64x64. Embedded-producer pipeline, sync granularity = 2 slices:
// 2 groups x 2 slice-buffers; one barrier handshake + 4-TMA refill per pair.
// ---------------------------------------------------------------------------
__global__ void __launch_bounds__(256, 1)
gemm_f16_mma_kernel(const __grid_constant__ CUtensorMap tma_a,
                    const __grid_constant__ CUtensorMap tma_b,
                    const float* __restrict__ bias,
                    const float* __restrict__ sa, const float* __restrict__ sbp,
                    float* __restrict__ C) {
    extern __shared__ char smem[];
    uint32_t sb = smem_u32(smem);
    int tid = threadIdx.x;
    int wid = tid >> 5;
    int lane = tid & 31;
    int wm = wid & 3;            // M offset wm*64
    int wn = wid >> 2;           // N offset wn*64
    int m_blk = blockIdx.y * BM;
    int n_blk = blockIdx.x * BN;

    if (tid == 0) {
#pragma unroll
        for (int g = 0; g < GROUPS; g++) {
            MBAR_INIT(sb + SMEM_FULL(g), 1);
            MBAR_INIT(sb + SMEM_EMPTY(g), 8);
        }
    }
    __syncthreads();

    // Prologue: fill both groups (pairs 0 and 1 -> slices 0..3).
    if (tid == 0) {
#pragma unroll
        for (int g = 0; g < GROUPS; g++) {
            MBAR_EXPECT_TX(sb + SMEM_FULL(g), PAIR_BYTES);
#pragma unroll
            for (int h = 0; h < 2; h++) {
                int sl = g * 2 + h;          // slice index == buffer index
                TMA_LOAD_2D(sb + SMEM_A_OFF(sl), &tma_a, sl * BKE, m_blk, sb + SMEM_FULL(g));
                TMA_LOAD_2D(sb + SMEM_B_OFF(sl), &tma_b, sl * BKE, n_blk, sb + SMEM_FULL(g));
            }
        }
    }

    // Per-lane ldmatrix addressing (SW128: phys 16B-chunk = chunk ^ (row & 7)).
    int r7 = lane & 7;
    int a_row = wm * 64 + ((lane >> 3) & 1) * 8 + r7;   // + f*16
    int a_hi  = (lane >> 4) & 1;
    int b_row = wn * 64 + ((lane >> 4) & 1) * 8 + r7;   // + g*16
    int b_hi  = (lane >> 3) & 1;

    float acc[4][8][4];
#pragma unroll
    for (int f = 0; f < 4; f++)
#pragma unroll
        for (int j = 0; j < 8; j++)
#pragma unroll
            for (int e = 0; e < 4; e++) acc[f][j][e] = 0.0f;

    int is_refiller = (wid == 0) ? (int)elect_one() : 0;

    int g = 0, ph = 0;
    int eph = 0;                 // refiller parity for empty barriers
    for (int p = 0; p < KPAIRS; p++) {
        // Refill the group consumed at pair p-1 with pair p+1 (slices 2(p+1), 2(p+1)+1).
        if (is_refiller && p > 0 && p + 1 < KPAIRS) {
            int ng = (p - 1) & 1;            // == (p+1) & 1
            MBAR_WAIT(sb + SMEM_EMPTY(ng), (uint32_t)eph);
            MBAR_EXPECT_TX(sb + SMEM_FULL(ng), PAIR_BYTES);
            int k0 = (p + 1) * 2;
#pragma unroll
            for (int h = 0; h < 2; h++) {
                int sl = ng * 2 + h;
                TMA_LOAD_2D(sb + SMEM_A_OFF(sl), &tma_a, (k0 + h) * BKE, m_blk, sb + SMEM_FULL(ng));
                TMA_LOAD_2D(sb + SMEM_B_OFF(sl), &tma_b, (k0 + h) * BKE, n_blk, sb + SMEM_FULL(ng));
            }
            if (ng == 1) eph ^= 1;
        }

        MBAR_WAIT(sb + SMEM_FULL(g), (uint32_t)ph);

#pragma unroll
        for (int h = 0; h < 2; h++) {
            int sl = g * 2 + h;
            uint32_t aBase = sb + SMEM_A_OFF(sl) + (uint32_t)a_row * 128;
            uint32_t bBase = sb + SMEM_B_OFF(sl) + (uint32_t)b_row * 128;

#pragma unroll
            for (int kc = 0; kc < KCH; kc++) {
                uint32_t aoff = (uint32_t)(((2 * kc + a_hi) ^ r7) << 4);
                uint32_t boff = (uint32_t)(((2 * kc + b_hi) ^ r7) << 4);

                uint32_t afr[4][4];
#pragma unroll
                for (int f = 0; f < 4; f++)
                    LDSM_X4(afr[f][0], afr[f][1], afr[f][2], afr[f][3],
                            aBase + (uint32_t)(f * 16 * 128) + aoff);

                uint32_t bfr[8][2];
#pragma unroll
                for (int q = 0; q < 4; q++) {
                    uint32_t t0, t1, t2, t3;
                    LDSM_X4(t0, t1, t2, t3, bBase + (uint32_t)(q * 16 * 128) + boff);
                    bfr[2 * q][0] = t0; bfr[2 * q][1] = t1;
                    bfr[2 * q + 1][0] = t2; bfr[2 * q + 1][1] = t3;
                }

#pragma unroll
                for (int f = 0; f < 4; f++)
#pragma unroll
                    for (int j = 0; j < 8; j++)
                        MMA_F16(acc[f][j], afr[f], bfr[j]);
            }
        }

        // Release this group (one arrive per warp; no CTA barrier).
        if (elect_one()) MBAR_ARRIVE(sb + SMEM_EMPTY(g));

        if (++g == GROUPS) { g = 0; ph ^= 1; }
    }

    // Epilogue: dequant + bias, float2 stores.
    float scale = __ldg(sa) * __ldg(sbp);
    int r = lane >> 2;
    int c2 = (lane & 3) * 2;
#pragma unroll
    for (int f = 0; f < 4; f++) {
        int row0 = m_blk + wm * 64 + f * 16 + r;
#pragma unroll
        for (int j = 0; j < 8; j++) {
            int col = n_blk + wn * 64 + j * 8 + c2;
            float2 bv = *reinterpret_cast<const float2*>(bias + col);
            float2 o0, o1;
            o0.x = acc[f][j][0] * scale + bv.x;
            o0.y = acc[f][j][1] * scale + bv.y;
            o1.x = acc[f][j][2] * scale + bv.x;
            o1.y = acc[f][j][3] * scale + bv.y;
            *reinterpret_cast<float2*>(C + (size_t)row0 * NN + col) = o0;
            *reinterpret_cast<float2*>(C + (size_t)(row0 + 8) * NN + col) = o1;
        }
    }
}

// ---------------------------------------------------------------------------
// Host launch
// ---------------------------------------------------------------------------
typedef CUresult (*EncodeTiledFn)(
    CUtensorMap*, CUtensorMapDataType, cuuint32_t, void*,
    const cuuint64_t*, const cuuint64_t*, const cuuint32_t*, const cuuint32_t*,
    CUtensorMapInterleave, CUtensorMapSwizzle, CUtensorMapL2promotion,
    CUtensorMapFloatOOBfill);

static void build_tmap_f16(EncodeTiledFn enc, CUtensorMap* out, void* ptr,
                           uint64_t dim0_elems, uint64_t dim1, uint32_t box_rows) {
    cuuint64_t dims[2] = {dim0_elems, dim1};
    cuuint64_t strides[1] = {dim0_elems * 2};   // bytes
    cuuint32_t box[2] = {BKE, box_rows};        // 64 f16 = 128B row
    cuuint32_t estr[2] = {1, 1};
    enc(out, CU_TENSOR_MAP_DATA_TYPE_FLOAT16, 2, ptr, dims, strides, box, estr,
        CU_TENSOR_MAP_INTERLEAVE_NONE, CU_TENSOR_MAP_SWIZZLE_128B,
        CU_TENSOR_MAP_L2_PROMOTION_L2_128B, CU_TENSOR_MAP_FLOAT_OOB_FILL_NONE);
}

extern "C" void kernel_launch(void* const* d_in, const int* in_sizes, int n_in,
                              void* d_out, int out_size) {
    const float* x      = (const float*)d_in[0];
    const int*   weight = (const int*)  d_in[1];
    const float* bias   = (const float*)d_in[2];
    const float* in_sc  = (const float*)d_in[3];
    const float* w_sc   = (const float*)d_in[4];
    float*       out    = (float*)d_out;

    __half* xh; cudaGetSymbolAddress((void**)&xh, g_xh);
    __half* wh; cudaGetSymbolAddress((void**)&wh, g_wh);

    // 1) merged prep: quantize (blocks 0..8191) + repack (blocks 8192..12287)
    prep_kernel<<<QBLOCKS + 4096, 256>>>(x, in_sc, weight);

    // 2) tensor-core GEMM (f16 HMMA, 256x128 CTA, paired-slice pipeline)
    {
        EncodeTiledFn enc = nullptr;
        cudaDriverEntryPointQueryResult qr;
        cudaGetDriverEntryPointByVersion("cuTensorMapEncodeTiled", (void**)&enc,
                                         12030, cudaEnableDefault, &qr);
        CUtensorMap tma_a, tma_b;
        build_tmap_f16(enc, &tma_a, xh, KK, MM, 256);
        build_tmap_f16(enc, &tma_b, wh, KK, NN, 128);

        cudaFuncSetAttribute(gemm_f16_mma_kernel,
                             cudaFuncAttributeMaxDynamicSharedMemorySize, SMEM_TOTAL);
        dim3 grid(NN / BN, MM / BM);
        gemm_f16_mma_kernel<<<grid, 256, SMEM_TOTAL>>>(tma_a, tma_b, bias,
                                                       in_sc, w_sc, out);
    }
}

// round 17
// speedup vs baseline: 1.1886x; 1.0040x over previous
#include <cuda_runtime.h>
#include <cuda.h>
#include <cuda_fp16.h>
#include <stdint.h>

// Problem sizes (fixed).
#define MM 8192
#define KK 4096
#define NN 4096

// GEMM tiling.
#define BM 256
#define BN 128
#define BKE 64                   // K elements (f16) per slice = 128 bytes
#define NSLOTS 4                 // slice buffers
#define GROUPS 2                 // barrier groups (2 slices each)
#define TILES_M (MM / BM)        // 32
#define TILES_N (NN / BN)        // 32
#define NTILES (TILES_M * TILES_N)  // 1024
#define PAIRS_PER_TILE 32        // 64 k-slices / 2
#define KCH 4                    // k16 chunks per slice
#define NCTAS 148                // persistent grid

// SMEM layout (dynamic):
//   [0..16)   full[2] mbarriers (tx, one per group)
//   [64..80)  empty[2] mbarriers (count 8)
//   [1024 + s*49152)          A slice buf: 256 rows x 128B (32KB, SW128)
//   [1024 + s*49152 + 32768)  B slice buf: 128 rows x 128B (16KB, SW128)
#define SMEM_FULL(g)  ((g) * 8)
#define SMEM_EMPTY(g) (64 + (g) * 8)
#define SMEM_A_OFF(s) (1024 + (s) * 49152)
#define SMEM_B_OFF(s) (1024 + (s) * 49152 + 32768)
#define SMEM_TOTAL    (1024 + NSLOTS * 49152)

#define PAIR_BYTES 98304u        // 2 slices x (32KB A + 16KB B)

// Scratch (allocation-free: __device__ globals). fp16 operands.
__device__ __align__(1024) __half g_xh[(size_t)MM * KK];   // A f16 [M][K]
__device__ __align__(1024) __half g_wh[(size_t)NN * KK];   // B f16 [N][K] (k contiguous)

// ---------------------------------------------------------------------------
// PTX helpers (plain sm_103-safe)
// ---------------------------------------------------------------------------
__device__ __forceinline__ uint32_t smem_u32(const void* p) {
    uint32_t a;
    asm("{ .reg .u64 t; cvta.to.shared.u64 t, %1; cvt.u32.u64 %0, t; }" : "=r"(a) : "l"(p));
    return a;
}
__device__ __forceinline__ uint32_t elect_one() {
    uint32_t p;
    asm volatile("{ .reg .pred q; elect.sync _|q, 0xFFFFFFFF; selp.b32 %0, 1, 0, q; }" : "=r"(p));
    return p;
}

#define MBAR_INIT(a, cnt) \
    asm volatile("mbarrier.init.shared.b64 [%0], %1;" :: "r"(a), "r"(cnt) : "memory")
#define MBAR_EXPECT_TX(a, bytes) \
    asm volatile("mbarrier.arrive.expect_tx.shared.b64 _, [%0], %1;" :: "r"(a), "r"(bytes) : "memory")
#define MBAR_ARRIVE(a) \
    asm volatile("mbarrier.arrive.release.cta.shared.b64 _, [%0];" :: "r"(a) : "memory")

#define MBAR_WAIT(a, ph) do {                                                   \
    uint32_t _m = (a), _p = (ph), _d;                                           \
    asm volatile("{ .reg .pred p; mbarrier.try_wait.parity.acquire.cta.shared::cta.b64 p, [%1], %2; selp.b32 %0, 1, 0, p; }" \
        : "=r"(_d) : "r"(_m), "r"(_p) : "memory");                              \
    if (!_d) {                                                                  \
        asm volatile("{ .reg .pred P; L1_%=: mbarrier.try_wait.parity.acquire.cta.shared::cta.b64 P, [%0], %1, 0x989680; @P bra.uni L2_%=; bra.uni L1_%=; L2_%=: }" \
            :: "r"(_m), "r"(_p) : "memory");                                    \
    }                                                                           \
} while (0)

#define TMA_LOAD_2D(dst, map, cx, cy, bar) \
    asm volatile("cp.async.bulk.tensor.2d.shared::cta.global.tile.mbarrier::complete_tx::bytes [%0], [%1, {%2, %3}], [%4];" \
        :: "r"(dst), "l"(map), "r"(cx), "r"(cy), "r"(bar) : "memory")

#define LDSM_X4(r0, r1, r2, r3, addr) \
    asm volatile("ldmatrix.sync.aligned.m8n8.x4.shared.b16 {%0,%1,%2,%3}, [%4];" \
        : "=r"(r0), "=r"(r1), "=r"(r2), "=r"(r3) : "r"(addr))

// m16n8k16 f16 x f16 -> f32 accumulate.
#define MMA_F16(d, a, b) \
    asm volatile("mma.sync.aligned.m16n8k16.row.col.f32.f16.f16.f32 " \
        "{%0,%1,%2,%3}, {%4,%5,%6,%7}, {%8,%9}, {%0,%1,%2,%3};" \
        : "+f"((d)[0]), "+f"((d)[1]), "+f"((d)[2]), "+f"((d)[3]) \
        : "r"((a)[0]), "r"((a)[1]), "r"((a)[2]), "r"((a)[3]), "r"((b)[0]), "r"((b)[1]))

// ---------------------------------------------------------------------------
// Kernel 1 (merged prep): blocks [0, 8192) quantize x; blocks [8192, 12288)
// repack the weight. Concurrent execution fills HBM bandwidth gaps.
// ---------------------------------------------------------------------------
#define QBLOCKS 8192
#define QSTRIDE (QBLOCKS * 256)

__global__ void __launch_bounds__(256)
prep_kernel(const float* __restrict__ x,
            const float* __restrict__ scale_ptr,
            const int* __restrict__ w) {
    __shared__ __half sh[32][128 + 4];
    int bx = blockIdx.x;
    int tid = threadIdx.x;

    if (bx < QBLOCKS) {
        // ---- quantize x fp32 -> f16-of-int8 (round-half-even + clip) ----
        int base = bx * 256 + tid;
        float s = __ldg(scale_ptr);
        const float4* x4 = reinterpret_cast<const float4*>(x);
        uint2* o4 = reinterpret_cast<uint2*>(g_xh);
        float4 v[4];
#pragma unroll
        for (int u = 0; u < 4; u++) v[u] = x4[base + u * QSTRIDE];
#pragma unroll
        for (int u = 0; u < 4; u++) {
            int i = base + u * QSTRIDE;
            int a = __float2int_rn(v[u].x / s);
            int b = __float2int_rn(v[u].y / s);
            int c = __float2int_rn(v[u].z / s);
            int d = __float2int_rn(v[u].w / s);
            a = min(127, max(-128, a)); b = min(127, max(-128, b));
            c = min(127, max(-128, c)); d = min(127, max(-128, d));
            uint32_t h0 = (uint32_t)__half_as_ushort(__int2half_rn(a))
                        | ((uint32_t)__half_as_ushort(__int2half_rn(b)) << 16);
            uint32_t h1 = (uint32_t)__half_as_ushort(__int2half_rn(c))
                        | ((uint32_t)__half_as_ushort(__int2half_rn(d)) << 16);
            uint2 q; q.x = h0; q.y = h1;
            o4[i] = q;
        }
    } else {
        // ---- repack weight int32 [K][N] -> f16 [N][K] ----
        int rb = bx - QBLOCKS;                // 0..4095
        int n0 = (rb & 127) * 32;             // 128 n-blocks
        int k0 = (rb >> 7) * 128;             // 32 k-blocks
        int n = tid & 31, kb = tid >> 5;
#pragma unroll
        for (int i = 0; i < 16; i++) {
            int k = kb + i * 8;
            sh[n][k] = __int2half_rn(w[(size_t)(k0 + k) * NN + (n0 + n)]);
        }
        __syncthreads();
        int kq = tid & 31, nn = tid >> 5;
#pragma unroll
        for (int i = 0; i < 4; i++) {
            int n2 = nn + i * 8;
            uint2 v = *reinterpret_cast<const uint2*>(&sh[n2][kq * 4]);
            *reinterpret_cast<uint2*>(&g_wh[(size_t)(n0 + n2) * KK + k0 + kq * 4]) = v;
        }
    }
}

// ---------------------------------------------------------------------------
// Kernel 2: PERSISTENT f16 GEMM. 148 CTAs; each walks tiles bx + k*148.
// CTA tile 256x128, 256 threads = 8 warps (4M x 2N), warp tile 64x64.
// Continuous slice stream across tiles (32 pairs = 64 k-slices per tile):
// next tile's first TMA pair is issued before the current tile's epilogue.
// Stream pair s: buffer group s&1, full-parity (s>>1)&1.
// ---------------------------------------------------------------------------
__global__ void __launch_bounds__(256, 1)
gemm_f16_mma_kernel(const __grid_constant__ CUtensorMap tma_a,
                    const __grid_constant__ CUtensorMap tma_b,
                    const float* __restrict__ bias,
                    const float* __restrict__ sa, const float* __restrict__ sbp,
                    float* __restrict__ C) {
    extern __shared__ char smem[];
    uint32_t sb = smem_u32(smem);
    int tid = threadIdx.x;
    int wid = tid >> 5;
    int lane = tid & 31;
    int wm = wid & 3;            // M offset wm*64
    int wn = wid >> 2;           // N offset wn*64
    int bx = blockIdx.x;

    // My tile count and stream length (in pairs).
    int ntiles = (NTILES - bx + NCTAS - 1) / NCTAS;
    if (ntiles <= 0) return;
    int S = ntiles * PAIRS_PER_TILE;

    if (tid == 0) {
#pragma unroll
        for (int g = 0; g < GROUPS; g++) {
            MBAR_INIT(sb + SMEM_FULL(g), 1);
            MBAR_INIT(sb + SMEM_EMPTY(g), 8);
        }
    }
    __syncthreads();

    // Coords of stream pair sp: tile ti = sp/32, local pair lp = sp%32.
    // tile_g = bx + ti*NCTAS; m_blk = (tile_g>>5)*BM; n_blk = (tile_g&31)*BN.
    // k slices: lp*2, lp*2+1.
#define PAIR_LOAD(sp, grp) do {                                                  \
    int _ti = (sp) >> 5;                                                         \
    int _lp = (sp) & 31;                                                         \
    int _tg = bx + _ti * NCTAS;                                                  \
    int _mb = (_tg >> 5) * BM;                                                   \
    int _nb = (_tg & 31) * BN;                                                   \
    MBAR_EXPECT_TX(sb + SMEM_FULL(grp), PAIR_BYTES);                             \
    _Pragma("unroll")                                                            \
    for (int _h = 0; _h < 2; _h++) {                                             \
        int _sl = (grp) * 2 + _h;                                                \
        int _k = _lp * 2 + _h;                                                   \
        TMA_LOAD_2D(sb + SMEM_A_OFF(_sl), &tma_a, _k * BKE, _mb, sb + SMEM_FULL(grp)); \
        TMA_LOAD_2D(sb + SMEM_B_OFF(_sl), &tma_b, _k * BKE, _nb, sb + SMEM_FULL(grp)); \
    }                                                                            \
} while (0)

    // Prologue: stream pairs 0 and 1.
    if (tid == 0) {
        PAIR_LOAD(0, 0);
        if (S > 1) PAIR_LOAD(1, 1);
    }

    // Per-lane ldmatrix addressing (SW128: phys 16B-chunk = chunk ^ (row & 7)).
    int r7 = lane & 7;
    int a_row = wm * 64 + ((lane >> 3) & 1) * 8 + r7;   // + f*16
    int a_hi  = (lane >> 4) & 1;
    int b_row = wn * 64 + ((lane >> 4) & 1) * 8 + r7;   // + g*16
    int b_hi  = (lane >> 3) & 1;

    int is_refiller = (wid == 0) ? (int)elect_one() : 0;
    float scale = __ldg(sa) * __ldg(sbp);
    int er = lane >> 2;
    int ec2 = (lane & 3) * 2;

    int s_ctr = 0;               // global stream pair counter
    int ph = 0, eph = 0;         // running parities (full / empty)

    for (int ti = 0; ti < ntiles; ti++) {
        int tile_g = bx + ti * NCTAS;
        int m_blk = (tile_g >> 5) * BM;
        int n_blk = (tile_g & 31) * BN;

        float acc[4][8][4];
#pragma unroll
        for (int f = 0; f < 4; f++)
#pragma unroll
            for (int j = 0; j < 8; j++)
#pragma unroll
                for (int e = 0; e < 4; e++) acc[f][j][e] = 0.0f;

        for (int p = 0; p < PAIRS_PER_TILE; p++) {
            int g = s_ctr & 1;

            // Refill: at stream pair s (>0), load stream pair s+1 into group
            // (s+1)&1 == (s-1)&1, waiting that group's empty at parity eph.
            if (is_refiller && s_ctr > 0 && s_ctr + 1 < S) {
                int ng = (s_ctr - 1) & 1;
                MBAR_WAIT(sb + SMEM_EMPTY(ng), (uint32_t)eph);
                PAIR_LOAD(s_ctr + 1, ng);
                if (ng == 1) eph ^= 1;
            }

            MBAR_WAIT(sb + SMEM_FULL(g), (uint32_t)ph);

#pragma unroll
            for (int h = 0; h < 2; h++) {
                int sl = g * 2 + h;
                uint32_t aBase = sb + SMEM_A_OFF(sl) + (uint32_t)a_row * 128;
                uint32_t bBase = sb + SMEM_B_OFF(sl) + (uint32_t)b_row * 128;

#pragma unroll
                for (int kc = 0; kc < KCH; kc++) {
                    uint32_t aoff = (uint32_t)(((2 * kc + a_hi) ^ r7) << 4);
                    uint32_t boff = (uint32_t)(((2 * kc + b_hi) ^ r7) << 4);

                    uint32_t afr[4][4];
#pragma unroll
                    for (int f = 0; f < 4; f++)
                        LDSM_X4(afr[f][0], afr[f][1], afr[f][2], afr[f][3],
                                aBase + (uint32_t)(f * 16 * 128) + aoff);

                    uint32_t bfr[8][2];
#pragma unroll
                    for (int q = 0; q < 4; q++) {
                        uint32_t t0, t1, t2, t3;
                        LDSM_X4(t0, t1, t2, t3, bBase + (uint32_t)(q * 16 * 128) + boff);
                        bfr[2 * q][0] = t0; bfr[2 * q][1] = t1;
                        bfr[2 * q + 1][0] = t2; bfr[2 * q + 1][1] = t3;
                    }

#pragma unroll
                    for (int f = 0; f < 4; f++)
#pragma unroll
                        for (int j = 0; j < 8; j++)
                            MMA_F16(acc[f][j], afr[f], bfr[j]);
                }
            }

            // Release this group (one arrive per warp; no CTA barrier).
            if (elect_one()) MBAR_ARRIVE(sb + SMEM_EMPTY(g));

            s_ctr++;
            if ((s_ctr & 1) == 0) ph ^= 1;   // flip after both groups consumed
        }

        // Epilogue for this tile: dequant + bias, float2 stores.
        // Next tile's first TMA pair is already in flight (issued at s_ctr-1).
#pragma unroll
        for (int f = 0; f < 4; f++) {
            int row0 = m_blk + wm * 64 + f * 16 + er;
#pragma unroll
            for (int j = 0; j < 8; j++) {
                int col = n_blk + wn * 64 + j * 8 + ec2;
                float2 bv = *reinterpret_cast<const float2*>(bias + col);
                float2 o0, o1;
                o0.x = acc[f][j][0] * scale + bv.x;
                o0.y = acc[f][j][1] * scale + bv.y;
                o1.x = acc[f][j][2] * scale + bv.x;
                o1.y = acc[f][j][3] * scale + bv.y;
                *reinterpret_cast<float2*>(C + (size_t)row0 * NN + col) = o0;
                *reinterpret_cast<float2*>(C + (size_t)(row0 + 8) * NN + col) = o1;
            }
        }
    }
#undef PAIR_LOAD
}

// ---------------------------------------------------------------------------
// Host launch
// ---------------------------------------------------------------------------
typedef CUresult (*EncodeTiledFn)(
    CUtensorMap*, CUtensorMapDataType, cuuint32_t, void*,
    const cuuint64_t*, const cuuint64_t*, const cuuint32_t*, const cuuint32_t*,
    CUtensorMapInterleave, CUtensorMapSwizzle, CUtensorMapL2promotion,
    CUtensorMapFloatOOBfill);

static void build_tmap_f16(EncodeTiledFn enc, CUtensorMap* out, void* ptr,
                           uint64_t dim0_elems, uint64_t dim1, uint32_t box_rows) {
    cuuint64_t dims[2] = {dim0_elems, dim1};
    cuuint64_t strides[1] = {dim0_elems * 2};   // bytes
    cuuint32_t box[2] = {BKE, box_rows};        // 64 f16 = 128B row
    cuuint32_t estr[2] = {1, 1};
    enc(out, CU_TENSOR_MAP_DATA_TYPE_FLOAT16, 2, ptr, dims, strides, box, estr,
        CU_TENSOR_MAP_INTERLEAVE_NONE, CU_TENSOR_MAP_SWIZZLE_128B,
        CU_TENSOR_MAP_L2_PROMOTION_L2_128B, CU_TENSOR_MAP_FLOAT_OOB_FILL_NONE);
}

extern "C" void kernel_launch(void* const* d_in, const int* in_sizes, int n_in,
                              void* d_out, int out_size) {
    const float* x      = (const float*)d_in[0];
    const int*   weight = (const int*)  d_in[1];
    const float* bias   = (const float*)d_in[2];
    const float* in_sc  = (const float*)d_in[3];
    const float* w_sc   = (const float*)d_in[4];
    float*       out    = (float*)d_out;

    __half* xh; cudaGetSymbolAddress((void**)&xh, g_xh);
    __half* wh; cudaGetSymbolAddress((void**)&wh, g_wh);

    // 1) merged prep: quantize (blocks 0..8191) + repack (blocks 8192..12287)
    prep_kernel<<<QBLOCKS + 4096, 256>>>(x, in_sc, weight);

    // 2) persistent tensor-core GEMM (f16 HMMA, 256x128 tiles, 148 CTAs)
    {
        EncodeTiledFn enc = nullptr;
        cudaDriverEntryPointQueryResult qr;
        cudaGetDriverEntryPointByVersion("cuTensorMapEncodeTiled", (void**)&enc,
                                         12030, cudaEnableDefault, &qr);
        CUtensorMap tma_a, tma_b;
        build_tmap_f16(enc, &tma_a, xh, KK, MM, 256);
        build_tmap_f16(enc, &tma_b, wh, KK, NN, 128);

        cudaFuncSetAttribute(gemm_f16_mma_kernel,
                             cudaFuncAttributeMaxDynamicSharedMemorySize, SMEM_TOTAL);
        gemm_f16_mma_kernel<<<NCTAS, 256, SMEM_TOTAL>>>(tma_a, tma_b, bias,
                                                        in_sc, w_sc, out);
    }
}